// round 1
// baseline (speedup 1.0000x reference)
#include <cuda_runtime.h>
#include <cstdint>

#define NB 64
#define NT 256
#define NC 384
#define NH 6
#define ND 64
#define BTOK (NB*NT)                 // 16384 tokens
#define BHTD (NB*NH*NT*ND)           // 6,291,456 elements per q/k/v

// Scratch (no allocations allowed): q,k,v then attention output [B,T,H*D]
__device__ float g_qkv[3ull * BHTD];             // ~75.5 MB
__device__ float g_ao[(size_t)BTOK * NC];        // ~25.2 MB

__device__ __forceinline__ uint32_t f2tf(float f) {
    uint32_t u;
    asm("cvt.rna.tf32.f32 %0, %1;" : "=r"(u) : "f"(f));
    return u;
}

__device__ __forceinline__ void mma_tf32(float d[4], const uint32_t a[4], const uint32_t b[2]) {
    asm volatile(
        "mma.sync.aligned.m16n8k8.row.col.f32.tf32.tf32.f32 "
        "{%0,%1,%2,%3}, {%4,%5,%6,%7}, {%8,%9}, {%0,%1,%2,%3};"
        : "+f"(d[0]), "+f"(d[1]), "+f"(d[2]), "+f"(d[3])
        : "r"(a[0]), "r"(a[1]), "r"(a[2]), "r"(a[3]), "r"(b[0]), "r"(b[1]));
}

// ---------------------------------------------------------------------------
// Kernel 1: QKV projection. grid (256 m-tiles, 6 heads, 3 mats), 128 threads.
// C[64x64] = A[64x384] * W[384x64]; A = x rows, W = W{q,k,v}[h].
// Output to g_qkv as [z][B,H,T,D].
// ---------------------------------------------------------------------------
__global__ __launch_bounds__(128) void qkv_gemm(
    const float* __restrict__ x,
    const float* __restrict__ Wq, const float* __restrict__ Wk, const float* __restrict__ Wv)
{
    __shared__ uint32_t As[64][36];   // [m][k], tf32, pad to 36 for bank-free frag reads
    __shared__ uint32_t Bs[32][68];   // [k][n], tf32

    const int tid = threadIdx.x, lane = tid & 31, warp = tid >> 5;
    const int gid = lane >> 2, tig = lane & 3;
    const int m0 = blockIdx.x * 64;
    const int h = blockIdx.y, z = blockIdx.z;
    const float* W = (z == 0 ? Wq : (z == 1 ? Wk : Wv)) + (size_t)h * NC * ND;

    const int wm = (warp >> 1) * 32, wn = (warp & 1) * 32;

    float acc[2][4][4];
#pragma unroll
    for (int mt = 0; mt < 2; mt++)
#pragma unroll
        for (int nt = 0; nt < 4; nt++)
#pragma unroll
            for (int q = 0; q < 4; q++) acc[mt][nt][q] = 0.f;

    for (int k0 = 0; k0 < NC; k0 += 32) {
        // A tile: 64 rows x 32 cols
#pragma unroll
        for (int i = 0; i < 4; i++) {
            int idx = tid + i * 128;
            int r = idx >> 3, c = (idx & 7) * 4;
            float4 v = *(const float4*)(x + (size_t)(m0 + r) * NC + k0 + c);
            As[r][c] = f2tf(v.x); As[r][c + 1] = f2tf(v.y);
            As[r][c + 2] = f2tf(v.z); As[r][c + 3] = f2tf(v.w);
        }
        // B tile: 32 rows (k) x 64 cols (n), ldb = 64
#pragma unroll
        for (int i = 0; i < 4; i++) {
            int idx = tid + i * 128;
            int r = idx >> 4, c = (idx & 15) * 4;
            float4 v = *(const float4*)(W + (size_t)(k0 + r) * ND + c);
            Bs[r][c] = f2tf(v.x); Bs[r][c + 1] = f2tf(v.y);
            Bs[r][c + 2] = f2tf(v.z); Bs[r][c + 3] = f2tf(v.w);
        }
        __syncthreads();

#pragma unroll
        for (int kk = 0; kk < 4; kk++) {
            const int kb = kk * 8;
            uint32_t af[2][4], bf[4][2];
#pragma unroll
            for (int mt = 0; mt < 2; mt++) {
                int r = wm + mt * 16 + gid;
                af[mt][0] = As[r][kb + tig];
                af[mt][1] = As[r + 8][kb + tig];
                af[mt][2] = As[r][kb + tig + 4];
                af[mt][3] = As[r + 8][kb + tig + 4];
            }
#pragma unroll
            for (int nt = 0; nt < 4; nt++) {
                int n = wn + nt * 8 + gid;
                bf[nt][0] = Bs[kb + tig][n];
                bf[nt][1] = Bs[kb + tig + 4][n];
            }
#pragma unroll
            for (int mt = 0; mt < 2; mt++)
#pragma unroll
                for (int nt = 0; nt < 4; nt++)
                    mma_tf32(acc[mt][nt], af[mt], bf[nt]);
        }
        __syncthreads();
    }

    // Epilogue: out[z][(b*NH+h)*NT + t][d]
    const int b = m0 / NT, t0 = m0 % NT;
    float* outp = g_qkv + (size_t)z * BHTD + ((size_t)(b * NH + h) * NT + t0) * ND;
#pragma unroll
    for (int mt = 0; mt < 2; mt++)
#pragma unroll
        for (int nt = 0; nt < 4; nt++) {
            int r = wm + mt * 16 + gid;
            int c = wn + nt * 8 + 2 * tig;
            *(float2*)(outp + (size_t)r * ND + c) = make_float2(acc[mt][nt][0], acc[mt][nt][1]);
            *(float2*)(outp + (size_t)(r + 8) * ND + c) = make_float2(acc[mt][nt][2], acc[mt][nt][3]);
        }
}

// ---------------------------------------------------------------------------
// Kernel 2: causal flash attention per (b,h). grid (6, 64), 256 threads.
// K,V resident in SMEM (tf32). Q tiles of 128 rows, key tiles of 64.
// ---------------------------------------------------------------------------
#define ATTN_SMEM ((512 * 68 + 128 * 68) * 4)   // Ks + Vs + Ps = 174,080 B

__global__ __launch_bounds__(256) void attn_kernel()
{
    extern __shared__ uint32_t sh[];
    uint32_t* Ks = sh;                 // [256][68]
    uint32_t* Vs = sh + 256 * 68;      // [256][68]
    uint32_t* Ps = sh + 512 * 68;      // [128][68], per-warp-private rows

    const int tid = threadIdx.x, lane = tid & 31, warp = tid >> 5;
    const int gid = lane >> 2, tig = lane & 3;
    const int h = blockIdx.x, b = blockIdx.y;

    const float* qb = g_qkv + ((size_t)(b * NH + h) * NT) * ND;
    const float* kbp = qb + BHTD;
    const float* vbp = qb + 2ull * BHTD;

    // Stage K,V into SMEM as tf32
    for (int i = tid; i < NT * ND / 4; i += 256) {
        int r = i >> 4, c = (i & 15) * 4;
        float4 kv = *(const float4*)(kbp + (size_t)r * ND + c);
        Ks[r * 68 + c] = f2tf(kv.x); Ks[r * 68 + c + 1] = f2tf(kv.y);
        Ks[r * 68 + c + 2] = f2tf(kv.z); Ks[r * 68 + c + 3] = f2tf(kv.w);
        float4 vv = *(const float4*)(vbp + (size_t)r * ND + c);
        Vs[r * 68 + c] = f2tf(vv.x); Vs[r * 68 + c + 1] = f2tf(vv.y);
        Vs[r * 68 + c + 2] = f2tf(vv.z); Vs[r * 68 + c + 3] = f2tf(vv.w);
    }
    __syncthreads();

    const int wr = warp * 16;   // warp's row origin inside the 128-row q tile

    for (int i = 0; i < 2; i++) {
        // Q fragments (scaled by 1/sqrt(D), exact power of two)
        uint32_t qf[8][4];
        const int qr0 = i * 128 + wr + gid;
#pragma unroll
        for (int kk = 0; kk < 8; kk++) {
            qf[kk][0] = f2tf(0.125f * qb[(size_t)qr0 * ND + kk * 8 + tig]);
            qf[kk][1] = f2tf(0.125f * qb[(size_t)(qr0 + 8) * ND + kk * 8 + tig]);
            qf[kk][2] = f2tf(0.125f * qb[(size_t)qr0 * ND + kk * 8 + tig + 4]);
            qf[kk][3] = f2tf(0.125f * qb[(size_t)(qr0 + 8) * ND + kk * 8 + tig + 4]);
        }

        float oacc[8][4];
#pragma unroll
        for (int nt = 0; nt < 8; nt++)
#pragma unroll
            for (int q = 0; q < 4; q++) oacc[nt][q] = 0.f;
        float m0r = -1e30f, m1r = -1e30f, l0 = 0.f, l1 = 0.f;

        const int jmax = 2 * i + 1;
        for (int j = 0; j <= jmax; j++) {
            // S = Q * K^T   (64 keys in tile j)
            float sacc[8][4];
#pragma unroll
            for (int nt = 0; nt < 8; nt++)
#pragma unroll
                for (int q = 0; q < 4; q++) sacc[nt][q] = 0.f;

#pragma unroll
            for (int kk = 0; kk < 8; kk++) {
                const int kb = kk * 8;
#pragma unroll
                for (int nt = 0; nt < 8; nt++) {
                    uint32_t bf[2];
                    int krow = j * 64 + nt * 8 + gid;
                    bf[0] = Ks[krow * 68 + kb + tig];
                    bf[1] = Ks[krow * 68 + kb + tig + 4];
                    mma_tf32(sacc[nt], qf[kk], bf);
                }
            }

            // Causal mask (only tiles overlapping the diagonal)
            const int qg0 = i * 128 + wr + gid, qg1 = qg0 + 8;
            if (j * 64 + 63 > i * 128) {
#pragma unroll
                for (int nt = 0; nt < 8; nt++) {
                    int kg = j * 64 + nt * 8 + 2 * tig;
                    if (kg > qg0) sacc[nt][0] = -1e30f;
                    if (kg + 1 > qg0) sacc[nt][1] = -1e30f;
                    if (kg > qg1) sacc[nt][2] = -1e30f;
                    if (kg + 1 > qg1) sacc[nt][3] = -1e30f;
                }
            }

            // Online softmax: row max
            float mx0 = -1e30f, mx1 = -1e30f;
#pragma unroll
            for (int nt = 0; nt < 8; nt++) {
                mx0 = fmaxf(mx0, fmaxf(sacc[nt][0], sacc[nt][1]));
                mx1 = fmaxf(mx1, fmaxf(sacc[nt][2], sacc[nt][3]));
            }
            mx0 = fmaxf(mx0, __shfl_xor_sync(0xffffffffu, mx0, 1));
            mx0 = fmaxf(mx0, __shfl_xor_sync(0xffffffffu, mx0, 2));
            mx1 = fmaxf(mx1, __shfl_xor_sync(0xffffffffu, mx1, 1));
            mx1 = fmaxf(mx1, __shfl_xor_sync(0xffffffffu, mx1, 2));

            float mn0 = fmaxf(m0r, mx0), mn1 = fmaxf(m1r, mx1);
            float sf0 = __expf(m0r - mn0), sf1 = __expf(m1r - mn1);
            m0r = mn0; m1r = mn1;

            float rs0 = 0.f, rs1 = 0.f;
            const int prow = wr + gid;
#pragma unroll
            for (int nt = 0; nt < 8; nt++) {
                float p0 = __expf(sacc[nt][0] - mn0);
                float p1 = __expf(sacc[nt][1] - mn0);
                float p2 = __expf(sacc[nt][2] - mn1);
                float p3 = __expf(sacc[nt][3] - mn1);
                rs0 += p0 + p1; rs1 += p2 + p3;
                int pc = nt * 8 + 2 * tig;
                Ps[prow * 68 + pc] = f2tf(p0);
                Ps[prow * 68 + pc + 1] = f2tf(p1);
                Ps[(prow + 8) * 68 + pc] = f2tf(p2);
                Ps[(prow + 8) * 68 + pc + 1] = f2tf(p3);
            }
            rs0 += __shfl_xor_sync(0xffffffffu, rs0, 1);
            rs0 += __shfl_xor_sync(0xffffffffu, rs0, 2);
            rs1 += __shfl_xor_sync(0xffffffffu, rs1, 1);
            rs1 += __shfl_xor_sync(0xffffffffu, rs1, 2);
            l0 = l0 * sf0 + rs0;
            l1 = l1 * sf1 + rs1;

#pragma unroll
            for (int nt = 0; nt < 8; nt++) {
                oacc[nt][0] *= sf0; oacc[nt][1] *= sf0;
                oacc[nt][2] *= sf1; oacc[nt][3] *= sf1;
            }
            __syncwarp();   // Ps writes visible to all lanes of this warp

            // O += P * V
#pragma unroll
            for (int kk = 0; kk < 8; kk++) {
                const int kb = kk * 8;
                uint32_t af[4];
                af[0] = Ps[prow * 68 + kb + tig];
                af[1] = Ps[(prow + 8) * 68 + kb + tig];
                af[2] = Ps[prow * 68 + kb + tig + 4];
                af[3] = Ps[(prow + 8) * 68 + kb + tig + 4];
#pragma unroll
                for (int nt = 0; nt < 8; nt++) {
                    uint32_t bf[2];
                    int vrow = j * 64 + kb + tig;
                    bf[0] = Vs[vrow * 68 + nt * 8 + gid];
                    bf[1] = Vs[(vrow + 4) * 68 + nt * 8 + gid];
                    mma_tf32(oacc[nt], af, bf);
                }
            }
            __syncwarp();   // all lanes done reading Ps before next j overwrites
        }

        // Epilogue: write [B,T,H*D] so out-proj is a plain GEMM
        const float inv0 = 1.f / l0, inv1 = 1.f / l1;
        float* op = g_ao + ((size_t)(b * NT) + i * 128) * NC + h * ND;
        const int r0 = wr + gid;
#pragma unroll
        for (int nt = 0; nt < 8; nt++) {
            int cc = nt * 8 + 2 * tig;
            *(float2*)(op + (size_t)r0 * NC + cc) =
                make_float2(oacc[nt][0] * inv0, oacc[nt][1] * inv0);
            *(float2*)(op + (size_t)(r0 + 8) * NC + cc) =
                make_float2(oacc[nt][2] * inv1, oacc[nt][3] * inv1);
        }
    }
}

// ---------------------------------------------------------------------------
// Kernel 3: output projection + bias. grid (256 m-tiles, 6 n-tiles), 128 thr.
// out[16384,384] = g_ao[16384,384] * Wp[384,384] + bp
// ---------------------------------------------------------------------------
__global__ __launch_bounds__(128) void proj_gemm(
    const float* __restrict__ Wp, const float* __restrict__ bp, float* __restrict__ out)
{
    __shared__ uint32_t As[64][36];
    __shared__ uint32_t Bs[32][68];

    const int tid = threadIdx.x, lane = tid & 31, warp = tid >> 5;
    const int gid = lane >> 2, tig = lane & 3;
    const int m0 = blockIdx.x * 64;
    const int n0 = blockIdx.y * 64;
    const int wm = (warp >> 1) * 32, wn = (warp & 1) * 32;

    float acc[2][4][4];
#pragma unroll
    for (int mt = 0; mt < 2; mt++)
#pragma unroll
        for (int nt = 0; nt < 4; nt++)
#pragma unroll
            for (int q = 0; q < 4; q++) acc[mt][nt][q] = 0.f;

    for (int k0 = 0; k0 < NC; k0 += 32) {
#pragma unroll
        for (int i = 0; i < 4; i++) {
            int idx = tid + i * 128;
            int r = idx >> 3, c = (idx & 7) * 4;
            float4 v = *(const float4*)(g_ao + (size_t)(m0 + r) * NC + k0 + c);
            As[r][c] = f2tf(v.x); As[r][c + 1] = f2tf(v.y);
            As[r][c + 2] = f2tf(v.z); As[r][c + 3] = f2tf(v.w);
        }
#pragma unroll
        for (int i = 0; i < 4; i++) {
            int idx = tid + i * 128;
            int r = idx >> 4, c = (idx & 15) * 4;
            float4 v = *(const float4*)(Wp + (size_t)(k0 + r) * NC + n0 + c);
            Bs[r][c] = f2tf(v.x); Bs[r][c + 1] = f2tf(v.y);
            Bs[r][c + 2] = f2tf(v.z); Bs[r][c + 3] = f2tf(v.w);
        }
        __syncthreads();

#pragma unroll
        for (int kk = 0; kk < 4; kk++) {
            const int kb = kk * 8;
            uint32_t af[2][4], bf[4][2];
#pragma unroll
            for (int mt = 0; mt < 2; mt++) {
                int r = wm + mt * 16 + gid;
                af[mt][0] = As[r][kb + tig];
                af[mt][1] = As[r + 8][kb + tig];
                af[mt][2] = As[r][kb + tig + 4];
                af[mt][3] = As[r + 8][kb + tig + 4];
            }
#pragma unroll
            for (int nt = 0; nt < 4; nt++) {
                int n = wn + nt * 8 + gid;
                bf[nt][0] = Bs[kb + tig][n];
                bf[nt][1] = Bs[kb + tig + 4][n];
            }
#pragma unroll
            for (int mt = 0; mt < 2; mt++)
#pragma unroll
                for (int nt = 0; nt < 4; nt++)
                    mma_tf32(acc[mt][nt], af[mt], bf[nt]);
        }
        __syncthreads();
    }

#pragma unroll
    for (int mt = 0; mt < 2; mt++)
#pragma unroll
        for (int nt = 0; nt < 4; nt++) {
            int r = wm + mt * 16 + gid;
            int c = n0 + wn + nt * 8 + 2 * tig;
            float b0 = bp[c], b1 = bp[c + 1];
            *(float2*)(out + (size_t)(m0 + r) * NC + c) =
                make_float2(acc[mt][nt][0] + b0, acc[mt][nt][1] + b1);
            *(float2*)(out + (size_t)(m0 + r + 8) * NC + c) =
                make_float2(acc[mt][nt][2] + b0, acc[mt][nt][3] + b1);
        }
}

// ---------------------------------------------------------------------------
extern "C" void kernel_launch(void* const* d_in, const int* in_sizes, int n_in,
                              void* d_out, int out_size)
{
    const float* x  = (const float*)d_in[0];
    const float* Wq = (const float*)d_in[1];
    const float* Wk = (const float*)d_in[2];
    const float* Wv = (const float*)d_in[3];
    const float* Wp = (const float*)d_in[4];
    const float* bp = (const float*)d_in[5];
    float* out = (float*)d_out;

    cudaFuncSetAttribute(attn_kernel, cudaFuncAttributeMaxDynamicSharedMemorySize, ATTN_SMEM);

    qkv_gemm<<<dim3(BTOK / 64, NH, 3), 128>>>(x, Wq, Wk, Wv);
    attn_kernel<<<dim3(NH, NB), 256, ATTN_SMEM>>>();
    proj_gemm<<<dim3(BTOK / 64, NC / 64), 128>>>(Wp, bp, out);
}

// round 2
// speedup vs baseline: 1.1015x; 1.1015x over previous
#include <cuda_runtime.h>
#include <cstdint>

#define NB 64
#define NT 256
#define NC 384
#define NH 6
#define ND 64
#define BTOK (NB*NT)                 // 16384 tokens
#define BHTD (NB*NH*NT*ND)           // 6,291,456 elements per q/k/v

// Scratch (no allocations allowed): q,k,v then attention output [B,T,H*D]
__device__ float g_qkv[3ull * BHTD];             // ~75.5 MB
__device__ float g_ao[(size_t)BTOK * NC];        // ~25.2 MB

__device__ __forceinline__ uint32_t f2tf(float f) {
    uint32_t u;
    asm("cvt.rna.tf32.f32 %0, %1;" : "=r"(u) : "f"(f));
    return u;
}

__device__ __forceinline__ void mma_tf32(float d[4], const uint32_t a[4], const uint32_t b[2]) {
    asm volatile(
        "mma.sync.aligned.m16n8k8.row.col.f32.tf32.tf32.f32 "
        "{%0,%1,%2,%3}, {%4,%5,%6,%7}, {%8,%9}, {%0,%1,%2,%3};"
        : "+f"(d[0]), "+f"(d[1]), "+f"(d[2]), "+f"(d[3])
        : "r"(a[0]), "r"(a[1]), "r"(a[2]), "r"(a[3]), "r"(b[0]), "r"(b[1]));
}

// ---------------------------------------------------------------------------
// Kernel 1: merged QKV projection GEMM.
//   C[16384 x 1152] = x[16384 x 384] * Wcat[384 x 1152]
// where Wcat columns = [Wq h0..h5 | Wk h0..h5 | Wv h0..h5], 64 cols per head.
// CTA tile 128x128, 4 warps, warp tile 64x64 (1 LDS.32 per mma).
// grid (128 m-tiles, 9 n-tiles), 128 threads.
// Output scattered to g_qkv as [z][B,H,T,D].
// ---------------------------------------------------------------------------
#define AP 20    // As pitch (uint32): (gid*20+tig)%32 all distinct -> conflict-free
#define BP 132   // Bs pitch: (tig*132+gid)%32 distinct -> conflict-free

__global__ __launch_bounds__(128) void qkv_gemm(
    const float* __restrict__ x,
    const float* __restrict__ Wq, const float* __restrict__ Wk, const float* __restrict__ Wv)
{
    __shared__ uint32_t As[128 * AP];   // [m][k], k-step 16
    __shared__ uint32_t Bs[16 * BP];    // [k][n]

    const int tid = threadIdx.x, lane = tid & 31, warp = tid >> 5;
    const int gid = lane >> 2, tig = lane & 3;
    const int m0 = blockIdx.x * 128;
    const int n0 = blockIdx.y * 128;
    const int z = n0 / NC;              // 0=q,1=k,2=v (128-tiles never straddle: 384=3*128)
    const int h0 = (n0 % NC) >> 6;      // first head in this 128-col tile
    const float* W = (z == 0 ? Wq : (z == 1 ? Wk : Wv));

    const int wm = (warp >> 1) * 64, wn = (warp & 1) * 64;

    float acc[4][8][4];
#pragma unroll
    for (int mt = 0; mt < 4; mt++)
#pragma unroll
        for (int nt = 0; nt < 8; nt++)
#pragma unroll
            for (int q = 0; q < 4; q++) acc[mt][nt][q] = 0.f;

    for (int k0 = 0; k0 < NC; k0 += 16) {
        // A tile: 128 rows x 16 k
#pragma unroll
        for (int i = 0; i < 4; i++) {
            int e = tid + i * 128;
            int r = e >> 2, c = (e & 3) * 4;
            float4 v = *(const float4*)(x + (size_t)(m0 + r) * NC + k0 + c);
            uint4 p;
            p.x = f2tf(v.x); p.y = f2tf(v.y); p.z = f2tf(v.z); p.w = f2tf(v.w);
            *(uint4*)&As[r * AP + c] = p;
        }
        // B tile: 16 k-rows x 128 n-cols; col c -> head h0+(c>>6), dim c&63
#pragma unroll
        for (int i = 0; i < 4; i++) {
            int e = tid + i * 128;
            int r = e >> 5, c = (e & 31) * 4;
            const float* src = W + ((size_t)(h0 + (c >> 6)) * NC + (k0 + r)) * ND + (c & 63);
            float4 v = *(const float4*)src;
            uint4 p;
            p.x = f2tf(v.x); p.y = f2tf(v.y); p.z = f2tf(v.z); p.w = f2tf(v.w);
            *(uint4*)&Bs[r * BP + c] = p;
        }
        __syncthreads();

#pragma unroll
        for (int kk = 0; kk < 2; kk++) {
            const int kb = kk * 8;
            uint32_t af[4][4], bf[8][2];
#pragma unroll
            for (int mt = 0; mt < 4; mt++) {
                int r = wm + mt * 16 + gid;
                af[mt][0] = As[r * AP + kb + tig];
                af[mt][1] = As[(r + 8) * AP + kb + tig];
                af[mt][2] = As[r * AP + kb + tig + 4];
                af[mt][3] = As[(r + 8) * AP + kb + tig + 4];
            }
#pragma unroll
            for (int nt = 0; nt < 8; nt++) {
                int n = wn + nt * 8 + gid;
                bf[nt][0] = Bs[(kb + tig) * BP + n];
                bf[nt][1] = Bs[(kb + tig + 4) * BP + n];
            }
#pragma unroll
            for (int mt = 0; mt < 4; mt++)
#pragma unroll
                for (int nt = 0; nt < 8; nt++)
                    mma_tf32(acc[mt][nt], af[mt], bf[nt]);
        }
        __syncthreads();
    }

    // Epilogue: scatter to g_qkv[z][(b*NH+h)*NT + t][d]
#pragma unroll
    for (int mt = 0; mt < 4; mt++) {
        int m = m0 + wm + mt * 16 + gid;
        int b = m >> 8, t = m & 255;
        int b2 = (m + 8) >> 8, t2 = (m + 8) & 255;
#pragma unroll
        for (int nt = 0; nt < 8; nt++) {
            int cl = wn + nt * 8 + 2 * tig;
            int h = h0 + (cl >> 6), d = cl & 63;
            float* p0 = g_qkv + (size_t)z * BHTD + (((size_t)b * NH + h) * NT + t) * ND + d;
            float* p1 = g_qkv + (size_t)z * BHTD + (((size_t)b2 * NH + h) * NT + t2) * ND + d;
            *(float2*)p0 = make_float2(acc[mt][nt][0], acc[mt][nt][1]);
            *(float2*)p1 = make_float2(acc[mt][nt][2], acc[mt][nt][3]);
        }
    }
}

// ---------------------------------------------------------------------------
// Kernel 2: causal flash attention per (b,h). grid (6, 64), 256 threads.
// K,V resident in SMEM (tf32). Q tiles of 128 rows, key tiles of 64.
// Per-warp causal tile bound: warp handling rows [wr, wr+16) of pass i only
// iterates key tiles j <= (i*128+wr+15)/64.
// ---------------------------------------------------------------------------
#define ATTN_SMEM ((512 * 68 + 128 * 68) * 4)   // Ks + Vs + Ps = 174,080 B

__global__ __launch_bounds__(256) void attn_kernel()
{
    extern __shared__ uint32_t sh[];
    uint32_t* Ks = sh;                 // [256][68]
    uint32_t* Vs = sh + 256 * 68;      // [256][68]
    uint32_t* Ps = sh + 512 * 68;      // [128][68], per-warp-private rows

    const int tid = threadIdx.x, lane = tid & 31, warp = tid >> 5;
    const int gid = lane >> 2, tig = lane & 3;
    const int h = blockIdx.x, b = blockIdx.y;

    const float* qb = g_qkv + ((size_t)(b * NH + h) * NT) * ND;
    const float* kbp = qb + BHTD;
    const float* vbp = qb + 2ull * BHTD;

    // Stage K,V into SMEM as tf32
    for (int i = tid; i < NT * ND / 4; i += 256) {
        int r = i >> 4, c = (i & 15) * 4;
        float4 kv = *(const float4*)(kbp + (size_t)r * ND + c);
        Ks[r * 68 + c] = f2tf(kv.x); Ks[r * 68 + c + 1] = f2tf(kv.y);
        Ks[r * 68 + c + 2] = f2tf(kv.z); Ks[r * 68 + c + 3] = f2tf(kv.w);
        float4 vv = *(const float4*)(vbp + (size_t)r * ND + c);
        Vs[r * 68 + c] = f2tf(vv.x); Vs[r * 68 + c + 1] = f2tf(vv.y);
        Vs[r * 68 + c + 2] = f2tf(vv.z); Vs[r * 68 + c + 3] = f2tf(vv.w);
    }
    __syncthreads();

    const int wr = warp * 16;   // warp's row origin inside the 128-row q tile

    for (int i = 0; i < 2; i++) {
        // Q fragments (scaled by 1/sqrt(D), exact power of two)
        uint32_t qf[8][4];
        const int qr0 = i * 128 + wr + gid;
#pragma unroll
        for (int kk = 0; kk < 8; kk++) {
            qf[kk][0] = f2tf(0.125f * qb[(size_t)qr0 * ND + kk * 8 + tig]);
            qf[kk][1] = f2tf(0.125f * qb[(size_t)(qr0 + 8) * ND + kk * 8 + tig]);
            qf[kk][2] = f2tf(0.125f * qb[(size_t)qr0 * ND + kk * 8 + tig + 4]);
            qf[kk][3] = f2tf(0.125f * qb[(size_t)(qr0 + 8) * ND + kk * 8 + tig + 4]);
        }

        float oacc[8][4];
#pragma unroll
        for (int nt = 0; nt < 8; nt++)
#pragma unroll
            for (int q = 0; q < 4; q++) oacc[nt][q] = 0.f;
        float m0r = -1e30f, m1r = -1e30f, l0 = 0.f, l1 = 0.f;

        const int jmax = (i * 128 + wr + 15) >> 6;   // per-warp causal bound
        for (int j = 0; j <= jmax; j++) {
            // S = Q * K^T   (64 keys in tile j)
            float sacc[8][4];
#pragma unroll
            for (int nt = 0; nt < 8; nt++)
#pragma unroll
                for (int q = 0; q < 4; q++) sacc[nt][q] = 0.f;

#pragma unroll
            for (int kk = 0; kk < 8; kk++) {
                const int kb = kk * 8;
#pragma unroll
                for (int nt = 0; nt < 8; nt++) {
                    uint32_t bf[2];
                    int krow = j * 64 + nt * 8 + gid;
                    bf[0] = Ks[krow * 68 + kb + tig];
                    bf[1] = Ks[krow * 68 + kb + tig + 4];
                    mma_tf32(sacc[nt], qf[kk], bf);
                }
            }

            // Causal mask (only tiles overlapping this warp's rows)
            const int qg0 = i * 128 + wr + gid, qg1 = qg0 + 8;
            if (j * 64 + 63 > i * 128 + wr) {
#pragma unroll
                for (int nt = 0; nt < 8; nt++) {
                    int kg = j * 64 + nt * 8 + 2 * tig;
                    if (kg > qg0) sacc[nt][0] = -1e30f;
                    if (kg + 1 > qg0) sacc[nt][1] = -1e30f;
                    if (kg > qg1) sacc[nt][2] = -1e30f;
                    if (kg + 1 > qg1) sacc[nt][3] = -1e30f;
                }
            }

            // Online softmax: row max
            float mx0 = -1e30f, mx1 = -1e30f;
#pragma unroll
            for (int nt = 0; nt < 8; nt++) {
                mx0 = fmaxf(mx0, fmaxf(sacc[nt][0], sacc[nt][1]));
                mx1 = fmaxf(mx1, fmaxf(sacc[nt][2], sacc[nt][3]));
            }
            mx0 = fmaxf(mx0, __shfl_xor_sync(0xffffffffu, mx0, 1));
            mx0 = fmaxf(mx0, __shfl_xor_sync(0xffffffffu, mx0, 2));
            mx1 = fmaxf(mx1, __shfl_xor_sync(0xffffffffu, mx1, 1));
            mx1 = fmaxf(mx1, __shfl_xor_sync(0xffffffffu, mx1, 2));

            float mn0 = fmaxf(m0r, mx0), mn1 = fmaxf(m1r, mx1);
            float sf0 = __expf(m0r - mn0), sf1 = __expf(m1r - mn1);
            m0r = mn0; m1r = mn1;

            float rs0 = 0.f, rs1 = 0.f;
            const int prow = wr + gid;
#pragma unroll
            for (int nt = 0; nt < 8; nt++) {
                float p0 = __expf(sacc[nt][0] - mn0);
                float p1 = __expf(sacc[nt][1] - mn0);
                float p2 = __expf(sacc[nt][2] - mn1);
                float p3 = __expf(sacc[nt][3] - mn1);
                rs0 += p0 + p1; rs1 += p2 + p3;
                int pc = nt * 8 + 2 * tig;
                Ps[prow * 68 + pc] = f2tf(p0);
                Ps[prow * 68 + pc + 1] = f2tf(p1);
                Ps[(prow + 8) * 68 + pc] = f2tf(p2);
                Ps[(prow + 8) * 68 + pc + 1] = f2tf(p3);
            }
            rs0 += __shfl_xor_sync(0xffffffffu, rs0, 1);
            rs0 += __shfl_xor_sync(0xffffffffu, rs0, 2);
            rs1 += __shfl_xor_sync(0xffffffffu, rs1, 1);
            rs1 += __shfl_xor_sync(0xffffffffu, rs1, 2);
            l0 = l0 * sf0 + rs0;
            l1 = l1 * sf1 + rs1;

#pragma unroll
            for (int nt = 0; nt < 8; nt++) {
                oacc[nt][0] *= sf0; oacc[nt][1] *= sf0;
                oacc[nt][2] *= sf1; oacc[nt][3] *= sf1;
            }
            __syncwarp();   // Ps writes visible to all lanes of this warp

            // O += P * V
#pragma unroll
            for (int kk = 0; kk < 8; kk++) {
                const int kb = kk * 8;
                uint32_t af[4];
                af[0] = Ps[prow * 68 + kb + tig];
                af[1] = Ps[(prow + 8) * 68 + kb + tig];
                af[2] = Ps[prow * 68 + kb + tig + 4];
                af[3] = Ps[(prow + 8) * 68 + kb + tig + 4];
#pragma unroll
                for (int nt = 0; nt < 8; nt++) {
                    uint32_t bf[2];
                    int vrow = j * 64 + kb + tig;
                    bf[0] = Vs[vrow * 68 + nt * 8 + gid];
                    bf[1] = Vs[(vrow + 4) * 68 + nt * 8 + gid];
                    mma_tf32(oacc[nt], af, bf);
                }
            }
            __syncwarp();   // all lanes done reading Ps before next j overwrites
        }

        // Epilogue: write [B,T,H*D] so out-proj is a plain GEMM
        const float inv0 = 1.f / l0, inv1 = 1.f / l1;
        float* op = g_ao + ((size_t)(b * NT) + i * 128) * NC + h * ND;
        const int r0 = wr + gid;
#pragma unroll
        for (int nt = 0; nt < 8; nt++) {
            int cc = nt * 8 + 2 * tig;
            *(float2*)(op + (size_t)r0 * NC + cc) =
                make_float2(oacc[nt][0] * inv0, oacc[nt][1] * inv0);
            *(float2*)(op + (size_t)(r0 + 8) * NC + cc) =
                make_float2(oacc[nt][2] * inv1, oacc[nt][3] * inv1);
        }
    }
}

// ---------------------------------------------------------------------------
// Kernel 3: output projection + bias, same 128x128 CTA / 64x64 warp tiling.
// out[16384,384] = g_ao[16384,384] * Wp[384,384] + bp
// grid (128 m-tiles, 3 n-tiles), 128 threads.
// ---------------------------------------------------------------------------
__global__ __launch_bounds__(128) void proj_gemm(
    const float* __restrict__ Wp, const float* __restrict__ bp, float* __restrict__ out)
{
    __shared__ uint32_t As[128 * AP];
    __shared__ uint32_t Bs[16 * BP];

    const int tid = threadIdx.x, lane = tid & 31, warp = tid >> 5;
    const int gid = lane >> 2, tig = lane & 3;
    const int m0 = blockIdx.x * 128;
    const int n0 = blockIdx.y * 128;
    const int wm = (warp >> 1) * 64, wn = (warp & 1) * 64;

    float acc[4][8][4];
#pragma unroll
    for (int mt = 0; mt < 4; mt++)
#pragma unroll
        for (int nt = 0; nt < 8; nt++)
#pragma unroll
            for (int q = 0; q < 4; q++) acc[mt][nt][q] = 0.f;

    for (int k0 = 0; k0 < NC; k0 += 16) {
#pragma unroll
        for (int i = 0; i < 4; i++) {
            int e = tid + i * 128;
            int r = e >> 2, c = (e & 3) * 4;
            float4 v = *(const float4*)(g_ao + (size_t)(m0 + r) * NC + k0 + c);
            uint4 p;
            p.x = f2tf(v.x); p.y = f2tf(v.y); p.z = f2tf(v.z); p.w = f2tf(v.w);
            *(uint4*)&As[r * AP + c] = p;
        }
#pragma unroll
        for (int i = 0; i < 4; i++) {
            int e = tid + i * 128;
            int r = e >> 5, c = (e & 31) * 4;
            float4 v = *(const float4*)(Wp + (size_t)(k0 + r) * NC + n0 + c);
            uint4 p;
            p.x = f2tf(v.x); p.y = f2tf(v.y); p.z = f2tf(v.z); p.w = f2tf(v.w);
            *(uint4*)&Bs[r * BP + c] = p;
        }
        __syncthreads();

#pragma unroll
        for (int kk = 0; kk < 2; kk++) {
            const int kb = kk * 8;
            uint32_t af[4][4], bf[8][2];
#pragma unroll
            for (int mt = 0; mt < 4; mt++) {
                int r = wm + mt * 16 + gid;
                af[mt][0] = As[r * AP + kb + tig];
                af[mt][1] = As[(r + 8) * AP + kb + tig];
                af[mt][2] = As[r * AP + kb + tig + 4];
                af[mt][3] = As[(r + 8) * AP + kb + tig + 4];
            }
#pragma unroll
            for (int nt = 0; nt < 8; nt++) {
                int n = wn + nt * 8 + gid;
                bf[nt][0] = Bs[(kb + tig) * BP + n];
                bf[nt][1] = Bs[(kb + tig + 4) * BP + n];
            }
#pragma unroll
            for (int mt = 0; mt < 4; mt++)
#pragma unroll
                for (int nt = 0; nt < 8; nt++)
                    mma_tf32(acc[mt][nt], af[mt], bf[nt]);
        }
        __syncthreads();
    }

#pragma unroll
    for (int mt = 0; mt < 4; mt++) {
        int r = wm + mt * 16 + gid;
#pragma unroll
        for (int nt = 0; nt < 8; nt++) {
            int c = n0 + wn + nt * 8 + 2 * tig;
            float b0 = bp[c], b1 = bp[c + 1];
            *(float2*)(out + (size_t)(m0 + r) * NC + c) =
                make_float2(acc[mt][nt][0] + b0, acc[mt][nt][1] + b1);
            *(float2*)(out + (size_t)(m0 + r + 8) * NC + c) =
                make_float2(acc[mt][nt][2] + b0, acc[mt][nt][3] + b1);
        }
    }
}

// ---------------------------------------------------------------------------
extern "C" void kernel_launch(void* const* d_in, const int* in_sizes, int n_in,
                              void* d_out, int out_size)
{
    const float* x  = (const float*)d_in[0];
    const float* Wq = (const float*)d_in[1];
    const float* Wk = (const float*)d_in[2];
    const float* Wv = (const float*)d_in[3];
    const float* Wp = (const float*)d_in[4];
    const float* bp = (const float*)d_in[5];
    float* out = (float*)d_out;

    cudaFuncSetAttribute(attn_kernel, cudaFuncAttributeMaxDynamicSharedMemorySize, ATTN_SMEM);

    qkv_gemm<<<dim3(BTOK / 128, 9), 128>>>(x, Wq, Wk, Wv);
    attn_kernel<<<dim3(NH, NB), 256, ATTN_SMEM>>>();
    proj_gemm<<<dim3(BTOK / 128, NC / 128), 128>>>(Wp, bp, out);
}

// round 3
// speedup vs baseline: 1.1994x; 1.0889x over previous
#include <cuda_runtime.h>
#include <cstdint>

#define NB 64
#define NT 256
#define NC 384
#define NH 6
#define ND 64
#define BTOK (NB*NT)                 // 16384 tokens
#define BHTD (NB*NH*NT*ND)           // 6,291,456 elements per q/k/v

__device__ float g_qkv[3ull * BHTD];             // ~75.5 MB scratch
__device__ float g_ao[(size_t)BTOK * NC];        // ~25.2 MB scratch

__device__ __forceinline__ uint32_t f2tf(float f) {
    uint32_t u;
    asm("cvt.rna.tf32.f32 %0, %1;" : "=r"(u) : "f"(f));
    return u;
}
__device__ __forceinline__ uint32_t b2tf(uint32_t b) {   // raw fp32 bits -> tf32 (RNA)
    uint32_t u;
    asm("cvt.rna.tf32.f32 %0, %1;" : "=r"(u) : "f"(__uint_as_float(b)));
    return u;
}

__device__ __forceinline__ void mma_tf32(float d[4], const uint32_t a[4], const uint32_t b[2]) {
    asm volatile(
        "mma.sync.aligned.m16n8k8.row.col.f32.tf32.tf32.f32 "
        "{%0,%1,%2,%3}, {%4,%5,%6,%7}, {%8,%9}, {%0,%1,%2,%3};"
        : "+f"(d[0]), "+f"(d[1]), "+f"(d[2]), "+f"(d[3])
        : "r"(a[0]), "r"(a[1]), "r"(a[2]), "r"(a[3]), "r"(b[0]), "r"(b[1]));
}

__device__ __forceinline__ void cpa16(uint32_t dst, const void* src) {
    asm volatile("cp.async.cg.shared.global [%0], [%1], 16;" :: "r"(dst), "l"(src));
}
__device__ __forceinline__ void cpa_commit() { asm volatile("cp.async.commit_group;"); }
__device__ __forceinline__ void cpa_wait1()  { asm volatile("cp.async.wait_group 1;"); }

// ---------------------------------------------------------------------------
// Pipelined tf32 GEMM core, CTA tile 128x128, 4 warps, warp tile 64x64.
// 3-stage cp.async pipeline; fp32 staged raw, converted to tf32 at frag load.
// ---------------------------------------------------------------------------
#define AP 20            // As pitch (words): conflict-free frag reads
#define BP 132           // Bs pitch (words)
#define AS_W (128 * AP)  // 2560 words
#define BS_W (16 * BP)   // 2112 words
#define STG_W (AS_W + BS_W)            // 4672 words / stage
#define GEMM_SMEM (3 * STG_W * 4)      // 56,064 B

#define KITERS (NC / 16)               // 24

// issue one stage of A (x rows) + B for qkv (B gather across heads)
__device__ __forceinline__ void qkv_issue(
    uint32_t sbase, const float* __restrict__ x, const float* __restrict__ W,
    int m0, int h0, int k0, int tid)
{
    uint32_t as = sbase;
    uint32_t bs = sbase + AS_W * 4;
#pragma unroll
    for (int i = 0; i < 4; i++) {
        int e = tid + i * 128;
        int r = e >> 2, c = (e & 3) * 4;
        cpa16(as + (r * AP + c) * 4, x + (size_t)(m0 + r) * NC + k0 + c);
    }
#pragma unroll
    for (int i = 0; i < 4; i++) {
        int e = tid + i * 128;
        int r = e >> 5, c = (e & 31) * 4;
        cpa16(bs + (r * BP + c) * 4,
              W + ((size_t)(h0 + (c >> 6)) * NC + (k0 + r)) * ND + (c & 63));
    }
}

__device__ __forceinline__ void proj_issue(
    uint32_t sbase, const float* __restrict__ A, const float* __restrict__ Wp,
    int m0, int n0, int k0, int tid)
{
    uint32_t as = sbase;
    uint32_t bs = sbase + AS_W * 4;
#pragma unroll
    for (int i = 0; i < 4; i++) {
        int e = tid + i * 128;
        int r = e >> 2, c = (e & 3) * 4;
        cpa16(as + (r * AP + c) * 4, A + (size_t)(m0 + r) * NC + k0 + c);
    }
#pragma unroll
    for (int i = 0; i < 4; i++) {
        int e = tid + i * 128;
        int r = e >> 5, c = (e & 31) * 4;
        cpa16(bs + (r * BP + c) * 4, Wp + (size_t)(k0 + r) * NC + n0 + c);
    }
}

// compute one 16-k step from staged buffers into acc
__device__ __forceinline__ void gemm_step(
    const uint32_t* __restrict__ As, const uint32_t* __restrict__ Bs,
    int wm, int wn, int gid, int tig, float acc[4][8][4])
{
#pragma unroll
    for (int kk = 0; kk < 2; kk++) {
        const int kb = kk * 8;
        uint32_t af[4][4], bf[8][2];
#pragma unroll
        for (int mt = 0; mt < 4; mt++) {
            int r = wm + mt * 16 + gid;
            af[mt][0] = b2tf(As[r * AP + kb + tig]);
            af[mt][1] = b2tf(As[(r + 8) * AP + kb + tig]);
            af[mt][2] = b2tf(As[r * AP + kb + tig + 4]);
            af[mt][3] = b2tf(As[(r + 8) * AP + kb + tig + 4]);
        }
#pragma unroll
        for (int nt = 0; nt < 8; nt++) {
            int n = wn + nt * 8 + gid;
            bf[nt][0] = b2tf(Bs[(kb + tig) * BP + n]);
            bf[nt][1] = b2tf(Bs[(kb + tig + 4) * BP + n]);
        }
#pragma unroll
        for (int mt = 0; mt < 4; mt++)
#pragma unroll
            for (int nt = 0; nt < 8; nt++)
                mma_tf32(acc[mt][nt], af[mt], bf[nt]);
    }
}

// ---------------------------------------------------------------------------
// Kernel 1: merged QKV projection. C[16384x1152] = x * [Wq|Wk|Wv] per head.
// grid (128, 9), 128 threads. Output scattered to g_qkv[z][B,H,T,D].
// ---------------------------------------------------------------------------
__global__ __launch_bounds__(128) void qkv_gemm(
    const float* __restrict__ x,
    const float* __restrict__ Wq, const float* __restrict__ Wk, const float* __restrict__ Wv)
{
    extern __shared__ uint32_t sh[];
    const int tid = threadIdx.x, lane = tid & 31, warp = tid >> 5;
    const int gid = lane >> 2, tig = lane & 3;
    const int m0 = blockIdx.x * 128;
    const int n0 = blockIdx.y * 128;
    const int z = n0 / NC;
    const int h0 = (n0 % NC) >> 6;
    const float* W = (z == 0 ? Wq : (z == 1 ? Wk : Wv));
    const int wm = (warp >> 1) * 64, wn = (warp & 1) * 64;
    const uint32_t sb = (uint32_t)__cvta_generic_to_shared(sh);

    float acc[4][8][4];
#pragma unroll
    for (int mt = 0; mt < 4; mt++)
#pragma unroll
        for (int nt = 0; nt < 8; nt++)
#pragma unroll
            for (int q = 0; q < 4; q++) acc[mt][nt][q] = 0.f;

    // prologue: stages 0,1
    qkv_issue(sb, x, W, m0, h0, 0, tid);  cpa_commit();
    qkv_issue(sb + STG_W * 4, x, W, m0, h0, 16, tid);  cpa_commit();

    for (int it = 0; it < KITERS; it++) {
        cpa_wait1();
        __syncthreads();
        if (it + 2 < KITERS)
            qkv_issue(sb + ((it + 2) % 3) * STG_W * 4, x, W, m0, h0, (it + 2) * 16, tid);
        cpa_commit();
        const uint32_t* buf = sh + (it % 3) * STG_W;
        gemm_step(buf, buf + AS_W, wm, wn, gid, tig, acc);
    }

    // Epilogue: scatter to g_qkv[z][(b*NH+h)*NT + t][d]
#pragma unroll
    for (int mt = 0; mt < 4; mt++) {
        int m = m0 + wm + mt * 16 + gid;
        int b = m >> 8, t = m & 255;
        int b2 = (m + 8) >> 8, t2 = (m + 8) & 255;
#pragma unroll
        for (int nt = 0; nt < 8; nt++) {
            int cl = wn + nt * 8 + 2 * tig;
            int h = h0 + (cl >> 6), d = cl & 63;
            float* p0 = g_qkv + (size_t)z * BHTD + (((size_t)b * NH + h) * NT + t) * ND + d;
            float* p1 = g_qkv + (size_t)z * BHTD + (((size_t)b2 * NH + h) * NT + t2) * ND + d;
            *(float2*)p0 = make_float2(acc[mt][nt][0], acc[mt][nt][1]);
            *(float2*)p1 = make_float2(acc[mt][nt][2], acc[mt][nt][3]);
        }
    }
}

// ---------------------------------------------------------------------------
// Kernel 2: causal flash attention per (b,h). grid (6, 64), 256 threads.
// ---------------------------------------------------------------------------
#define ATTN_SMEM ((512 * 68 + 128 * 68) * 4)   // Ks + Vs + Ps = 174,080 B

__global__ __launch_bounds__(256) void attn_kernel()
{
    extern __shared__ uint32_t sh[];
    uint32_t* Ks = sh;                 // [256][68]
    uint32_t* Vs = sh + 256 * 68;      // [256][68]
    uint32_t* Ps = sh + 512 * 68;      // [128][68], per-warp-private rows

    const int tid = threadIdx.x, lane = tid & 31, warp = tid >> 5;
    const int gid = lane >> 2, tig = lane & 3;
    const int h = blockIdx.x, b = blockIdx.y;

    const float* qb = g_qkv + ((size_t)(b * NH + h) * NT) * ND;
    const float* kbp = qb + BHTD;
    const float* vbp = qb + 2ull * BHTD;

    for (int i = tid; i < NT * ND / 4; i += 256) {
        int r = i >> 4, c = (i & 15) * 4;
        float4 kv = *(const float4*)(kbp + (size_t)r * ND + c);
        Ks[r * 68 + c] = f2tf(kv.x); Ks[r * 68 + c + 1] = f2tf(kv.y);
        Ks[r * 68 + c + 2] = f2tf(kv.z); Ks[r * 68 + c + 3] = f2tf(kv.w);
        float4 vv = *(const float4*)(vbp + (size_t)r * ND + c);
        Vs[r * 68 + c] = f2tf(vv.x); Vs[r * 68 + c + 1] = f2tf(vv.y);
        Vs[r * 68 + c + 2] = f2tf(vv.z); Vs[r * 68 + c + 3] = f2tf(vv.w);
    }
    __syncthreads();

    const int wr = warp * 16;

    for (int i = 0; i < 2; i++) {
        uint32_t qf[8][4];
        const int qr0 = i * 128 + wr + gid;
#pragma unroll
        for (int kk = 0; kk < 8; kk++) {
            qf[kk][0] = f2tf(0.125f * qb[(size_t)qr0 * ND + kk * 8 + tig]);
            qf[kk][1] = f2tf(0.125f * qb[(size_t)(qr0 + 8) * ND + kk * 8 + tig]);
            qf[kk][2] = f2tf(0.125f * qb[(size_t)qr0 * ND + kk * 8 + tig + 4]);
            qf[kk][3] = f2tf(0.125f * qb[(size_t)(qr0 + 8) * ND + kk * 8 + tig + 4]);
        }

        float oacc[8][4];
#pragma unroll
        for (int nt = 0; nt < 8; nt++)
#pragma unroll
            for (int q = 0; q < 4; q++) oacc[nt][q] = 0.f;
        float m0r = -1e30f, m1r = -1e30f, l0 = 0.f, l1 = 0.f;

        const int jmax = (i * 128 + wr + 15) >> 6;
        for (int j = 0; j <= jmax; j++) {
            float sacc[8][4];
#pragma unroll
            for (int nt = 0; nt < 8; nt++)
#pragma unroll
                for (int q = 0; q < 4; q++) sacc[nt][q] = 0.f;

#pragma unroll
            for (int kk = 0; kk < 8; kk++) {
                const int kb = kk * 8;
#pragma unroll
                for (int nt = 0; nt < 8; nt++) {
                    uint32_t bf[2];
                    int krow = j * 64 + nt * 8 + gid;
                    bf[0] = Ks[krow * 68 + kb + tig];
                    bf[1] = Ks[krow * 68 + kb + tig + 4];
                    mma_tf32(sacc[nt], qf[kk], bf);
                }
            }

            const int qg0 = i * 128 + wr + gid, qg1 = qg0 + 8;
            if (j * 64 + 63 > i * 128 + wr) {
#pragma unroll
                for (int nt = 0; nt < 8; nt++) {
                    int kg = j * 64 + nt * 8 + 2 * tig;
                    if (kg > qg0) sacc[nt][0] = -1e30f;
                    if (kg + 1 > qg0) sacc[nt][1] = -1e30f;
                    if (kg > qg1) sacc[nt][2] = -1e30f;
                    if (kg + 1 > qg1) sacc[nt][3] = -1e30f;
                }
            }

            float mx0 = -1e30f, mx1 = -1e30f;
#pragma unroll
            for (int nt = 0; nt < 8; nt++) {
                mx0 = fmaxf(mx0, fmaxf(sacc[nt][0], sacc[nt][1]));
                mx1 = fmaxf(mx1, fmaxf(sacc[nt][2], sacc[nt][3]));
            }
            mx0 = fmaxf(mx0, __shfl_xor_sync(0xffffffffu, mx0, 1));
            mx0 = fmaxf(mx0, __shfl_xor_sync(0xffffffffu, mx0, 2));
            mx1 = fmaxf(mx1, __shfl_xor_sync(0xffffffffu, mx1, 1));
            mx1 = fmaxf(mx1, __shfl_xor_sync(0xffffffffu, mx1, 2));

            float mn0 = fmaxf(m0r, mx0), mn1 = fmaxf(m1r, mx1);
            float sf0 = __expf(m0r - mn0), sf1 = __expf(m1r - mn1);
            m0r = mn0; m1r = mn1;

            float rs0 = 0.f, rs1 = 0.f;
            const int prow = wr + gid;
#pragma unroll
            for (int nt = 0; nt < 8; nt++) {
                float p0 = __expf(sacc[nt][0] - mn0);
                float p1 = __expf(sacc[nt][1] - mn0);
                float p2 = __expf(sacc[nt][2] - mn1);
                float p3 = __expf(sacc[nt][3] - mn1);
                rs0 += p0 + p1; rs1 += p2 + p3;
                int pc = nt * 8 + 2 * tig;
                Ps[prow * 68 + pc] = f2tf(p0);
                Ps[prow * 68 + pc + 1] = f2tf(p1);
                Ps[(prow + 8) * 68 + pc] = f2tf(p2);
                Ps[(prow + 8) * 68 + pc + 1] = f2tf(p3);
            }
            rs0 += __shfl_xor_sync(0xffffffffu, rs0, 1);
            rs0 += __shfl_xor_sync(0xffffffffu, rs0, 2);
            rs1 += __shfl_xor_sync(0xffffffffu, rs1, 1);
            rs1 += __shfl_xor_sync(0xffffffffu, rs1, 2);
            l0 = l0 * sf0 + rs0;
            l1 = l1 * sf1 + rs1;

#pragma unroll
            for (int nt = 0; nt < 8; nt++) {
                oacc[nt][0] *= sf0; oacc[nt][1] *= sf0;
                oacc[nt][2] *= sf1; oacc[nt][3] *= sf1;
            }
            __syncwarp();

#pragma unroll
            for (int kk = 0; kk < 8; kk++) {
                const int kb = kk * 8;
                uint32_t af[4];
                af[0] = Ps[prow * 68 + kb + tig];
                af[1] = Ps[(prow + 8) * 68 + kb + tig];
                af[2] = Ps[prow * 68 + kb + tig + 4];
                af[3] = Ps[(prow + 8) * 68 + kb + tig + 4];
#pragma unroll
                for (int nt = 0; nt < 8; nt++) {
                    uint32_t bf[2];
                    int vrow = j * 64 + kb + tig;
                    bf[0] = Vs[vrow * 68 + nt * 8 + gid];
                    bf[1] = Vs[(vrow + 4) * 68 + nt * 8 + gid];
                    mma_tf32(oacc[nt], af, bf);
                }
            }
            __syncwarp();
        }

        const float inv0 = 1.f / l0, inv1 = 1.f / l1;
        float* op = g_ao + ((size_t)(b * NT) + i * 128) * NC + h * ND;
        const int r0 = wr + gid;
#pragma unroll
        for (int nt = 0; nt < 8; nt++) {
            int cc = nt * 8 + 2 * tig;
            *(float2*)(op + (size_t)r0 * NC + cc) =
                make_float2(oacc[nt][0] * inv0, oacc[nt][1] * inv0);
            *(float2*)(op + (size_t)(r0 + 8) * NC + cc) =
                make_float2(oacc[nt][2] * inv1, oacc[nt][3] * inv1);
        }
    }
}

// ---------------------------------------------------------------------------
// Kernel 3: output projection + bias, pipelined like qkv_gemm.
// grid (128, 3), 128 threads.
// ---------------------------------------------------------------------------
__global__ __launch_bounds__(128) void proj_gemm(
    const float* __restrict__ Wp, const float* __restrict__ bp, float* __restrict__ out)
{
    extern __shared__ uint32_t sh[];
    const int tid = threadIdx.x, lane = tid & 31, warp = tid >> 5;
    const int gid = lane >> 2, tig = lane & 3;
    const int m0 = blockIdx.x * 128;
    const int n0 = blockIdx.y * 128;
    const int wm = (warp >> 1) * 64, wn = (warp & 1) * 64;
    const uint32_t sb = (uint32_t)__cvta_generic_to_shared(sh);

    float acc[4][8][4];
#pragma unroll
    for (int mt = 0; mt < 4; mt++)
#pragma unroll
        for (int nt = 0; nt < 8; nt++)
#pragma unroll
            for (int q = 0; q < 4; q++) acc[mt][nt][q] = 0.f;

    proj_issue(sb, g_ao, Wp, m0, n0, 0, tid);  cpa_commit();
    proj_issue(sb + STG_W * 4, g_ao, Wp, m0, n0, 16, tid);  cpa_commit();

    for (int it = 0; it < KITERS; it++) {
        cpa_wait1();
        __syncthreads();
        if (it + 2 < KITERS)
            proj_issue(sb + ((it + 2) % 3) * STG_W * 4, g_ao, Wp, m0, n0, (it + 2) * 16, tid);
        cpa_commit();
        const uint32_t* buf = sh + (it % 3) * STG_W;
        gemm_step(buf, buf + AS_W, wm, wn, gid, tig, acc);
    }

#pragma unroll
    for (int mt = 0; mt < 4; mt++) {
        int r = wm + mt * 16 + gid;
#pragma unroll
        for (int nt = 0; nt < 8; nt++) {
            int c = n0 + wn + nt * 8 + 2 * tig;
            float b0 = bp[c], b1 = bp[c + 1];
            *(float2*)(out + (size_t)(m0 + r) * NC + c) =
                make_float2(acc[mt][nt][0] + b0, acc[mt][nt][1] + b1);
            *(float2*)(out + (size_t)(m0 + r + 8) * NC + c) =
                make_float2(acc[mt][nt][2] + b0, acc[mt][nt][3] + b1);
        }
    }
}

// ---------------------------------------------------------------------------
extern "C" void kernel_launch(void* const* d_in, const int* in_sizes, int n_in,
                              void* d_out, int out_size)
{
    const float* x  = (const float*)d_in[0];
    const float* Wq = (const float*)d_in[1];
    const float* Wk = (const float*)d_in[2];
    const float* Wv = (const float*)d_in[3];
    const float* Wp = (const float*)d_in[4];
    const float* bp = (const float*)d_in[5];
    float* out = (float*)d_out;

    cudaFuncSetAttribute(qkv_gemm, cudaFuncAttributeMaxDynamicSharedMemorySize, GEMM_SMEM);
    cudaFuncSetAttribute(attn_kernel, cudaFuncAttributeMaxDynamicSharedMemorySize, ATTN_SMEM);
    cudaFuncSetAttribute(proj_gemm, cudaFuncAttributeMaxDynamicSharedMemorySize, GEMM_SMEM);

    qkv_gemm<<<dim3(BTOK / 128, 9), 128, GEMM_SMEM>>>(x, Wq, Wk, Wv);
    attn_kernel<<<dim3(NH, NB), 256, ATTN_SMEM>>>();
    proj_gemm<<<dim3(BTOK / 128, NC / 128), 128, GEMM_SMEM>>>(Wp, bp, out);
}